// round 1
// baseline (speedup 1.0000x reference)
#include <cuda_runtime.h>
#include <math.h>

// ---------------------------------------------------------------------------
// Problem constants (fixed shapes from reference)
// ---------------------------------------------------------------------------
#define BATCH   2
#define SEQ     2048
#define DMODEL  1024
#define NH      16
#define DH      64
#define DFFN    4096
#define ATT     256
#define ROWS    (BATCH * SEQ)   // 4096
#define LN_EPS  1e-5f

// 1/sqrt(2048)
#define ATT_SCALE 0.022097086912079608f

// ---------------------------------------------------------------------------
// Scratch (static device globals; no allocations allowed)
// ---------------------------------------------------------------------------
__device__ float g_Q  [ROWS * DMODEL];
__device__ float g_K  [ROWS * DMODEL];
__device__ float g_V  [ROWS * DMODEL];
__device__ float g_CTX[ROWS * DMODEL];
__device__ float g_SA [ROWS * DMODEL];   // also reused for FFN2 output
__device__ float g_X1 [ROWS * DMODEL];
__device__ float g_FF1[ROWS * DFFN];

// ---------------------------------------------------------------------------
// SGEMM: C[M,N] = A[M,K] @ W[K,N] + bias, optional exact-GELU epilogue.
// 128x128 block tile, BK=8, 256 threads, 8x8 microtile per thread.
// All dims are multiples of 128 (M) / 128 (N) / 8 (K) for this problem.
// ---------------------------------------------------------------------------
template <int GELU>
__global__ __launch_bounds__(256) void sgemm_kernel(
    const float* __restrict__ A, const float* __restrict__ W,
    const float* __restrict__ bias, float* __restrict__ C,
    int M, int N, int K)
{
    __shared__ float As[8][128];
    __shared__ float Bs[8][128];

    const int tid = threadIdx.x;
    const int tx  = tid & 15;         // 0..15  -> column groups
    const int ty  = tid >> 4;         // 0..15  -> row groups
    const int m0  = blockIdx.y * 128;
    const int n0  = blockIdx.x * 128;

    const float* Ab = A + (size_t)m0 * K;
    const float* Wb = W + n0;

    const int arow = tid >> 1;            // 0..127
    const int acol = (tid & 1) * 4;       // 0 or 4
    const int brow = tid >> 5;            // 0..7
    const int bcol = (tid & 31) * 4;      // 0..124

    float acc[8][8];
    #pragma unroll
    for (int i = 0; i < 8; i++)
        #pragma unroll
        for (int j = 0; j < 8; j++) acc[i][j] = 0.f;

    for (int k0 = 0; k0 < K; k0 += 8) {
        float4 av = *(const float4*)(Ab + (size_t)arow * K + k0 + acol);
        float4 bv = *(const float4*)(Wb + (size_t)(k0 + brow) * N + bcol);
        As[acol + 0][arow] = av.x;
        As[acol + 1][arow] = av.y;
        As[acol + 2][arow] = av.z;
        As[acol + 3][arow] = av.w;
        *(float4*)(&Bs[brow][bcol]) = bv;
        __syncthreads();

        #pragma unroll
        for (int kk = 0; kk < 8; kk++) {
            float a[8], b[8];
            *(float4*)(a)     = *(const float4*)(&As[kk][ty * 4]);
            *(float4*)(a + 4) = *(const float4*)(&As[kk][ty * 4 + 64]);
            *(float4*)(b)     = *(const float4*)(&Bs[kk][tx * 4]);
            *(float4*)(b + 4) = *(const float4*)(&Bs[kk][tx * 4 + 64]);
            #pragma unroll
            for (int i = 0; i < 8; i++)
                #pragma unroll
                for (int j = 0; j < 8; j++)
                    acc[i][j] += a[i] * b[j];
        }
        __syncthreads();
    }

    // epilogue
    const int cbase = n0 + tx * 4;
    float4 bia0 = *(const float4*)(bias + cbase);
    float4 bia1 = *(const float4*)(bias + cbase + 64);

    #pragma unroll
    for (int i = 0; i < 8; i++) {
        int r = m0 + ty * 4 + ((i < 4) ? i : (i + 60));
        float v[8];
        v[0] = acc[i][0] + bia0.x;  v[1] = acc[i][1] + bia0.y;
        v[2] = acc[i][2] + bia0.z;  v[3] = acc[i][3] + bia0.w;
        v[4] = acc[i][4] + bia1.x;  v[5] = acc[i][5] + bia1.y;
        v[6] = acc[i][6] + bia1.z;  v[7] = acc[i][7] + bia1.w;
        if (GELU) {
            #pragma unroll
            for (int j = 0; j < 8; j++)
                v[j] = 0.5f * v[j] * (1.0f + erff(v[j] * 0.7071067811865475f));
        }
        float* Cp = C + (size_t)r * N + cbase;
        *(float4*)(Cp)      = make_float4(v[0], v[1], v[2], v[3]);
        *(float4*)(Cp + 64) = make_float4(v[4], v[5], v[6], v[7]);
    }
}

// ---------------------------------------------------------------------------
// Banded attention. One block = (64 queries, one head, one batch).
// One thread per query; K/V tiles staged in shared memory.
// No max-subtraction needed: |score| <= ~25 -> exp() stays finite in fp32
// and softmax is shift-invariant.
// ---------------------------------------------------------------------------
__global__ __launch_bounds__(64) void attn_kernel(
    const float* __restrict__ Q, const float* __restrict__ Km,
    const float* __restrict__ Vm, float* __restrict__ CTX)
{
    __shared__ float4 Ks[64][16];
    __shared__ float4 Vs[64][16];

    const int t  = threadIdx.x;
    const int i0 = blockIdx.x * 64;
    const int h  = blockIdx.y;
    const int b  = blockIdx.z;
    const int i  = i0 + t;

    const size_t qoff = ((size_t)(b * SEQ + i) * DMODEL) + h * DH;

    float4 q[16], o[16];
    #pragma unroll
    for (int c = 0; c < 16; c++) {
        q[c] = *(const float4*)(Q + qoff + c * 4);
        o[c] = make_float4(0.f, 0.f, 0.f, 0.f);
    }
    float l = 0.f;

    const int jlo = max(0, i0 - ATT);                 // multiple of 64
    const int jhi = min(SEQ, i0 + 64 + ATT);          // multiple of 64, exclusive

    for (int jt = jlo; jt < jhi; jt += 64) {
        const size_t koff = ((size_t)(b * SEQ + jt + t) * DMODEL) + h * DH;
        #pragma unroll
        for (int c = 0; c < 16; c++) {
            Ks[t][c] = *(const float4*)(Km + koff + c * 4);
            Vs[t][c] = *(const float4*)(Vm + koff + c * 4);
        }
        __syncthreads();

        for (int jj = 0; jj < 64; jj++) {
            const int j = jt + jj;
            if ((i - j) <= ATT && (j - i) <= ATT) {
                float s = 0.f;
                #pragma unroll
                for (int c = 0; c < 16; c++) {
                    float4 kv = Ks[jj][c];
                    s += q[c].x * kv.x + q[c].y * kv.y
                       + q[c].z * kv.z + q[c].w * kv.w;
                }
                float p = __expf(s * ATT_SCALE);
                l += p;
                #pragma unroll
                for (int c = 0; c < 16; c++) {
                    float4 vv = Vs[jj][c];
                    o[c].x += p * vv.x; o[c].y += p * vv.y;
                    o[c].z += p * vv.z; o[c].w += p * vv.w;
                }
            }
        }
        __syncthreads();
    }

    const float inv = 1.f / l;
    #pragma unroll
    for (int c = 0; c < 16; c++) {
        *(float4*)(CTX + qoff + c * 4) =
            make_float4(o[c].x * inv, o[c].y * inv, o[c].z * inv, o[c].w * inv);
    }
}

// ---------------------------------------------------------------------------
// Fused residual add + LayerNorm over last dim (D=1024).
// One block per row; 256 threads, 4 elements each; two-pass (mean then var)
// matching the reference var = mean((x-mu)^2).
// ---------------------------------------------------------------------------
__global__ __launch_bounds__(256) void add_ln_kernel(
    const float* __restrict__ A, const float* __restrict__ R,
    const float* __restrict__ gamma, const float* __restrict__ beta,
    float* __restrict__ out)
{
    __shared__ float red1[8];
    __shared__ float red2[8];

    const int row = blockIdx.x;
    const int t   = threadIdx.x;
    const size_t off = (size_t)row * DMODEL;

    float4 a = *(const float4*)(A + off + t * 4);
    float4 r = *(const float4*)(R + off + t * 4);
    float x0 = a.x + r.x, x1 = a.y + r.y, x2 = a.z + r.z, x3 = a.w + r.w;

    float s = x0 + x1 + x2 + x3;
    #pragma unroll
    for (int oo = 16; oo; oo >>= 1) s += __shfl_xor_sync(0xffffffffu, s, oo);
    if ((t & 31) == 0) red1[t >> 5] = s;
    __syncthreads();

    float mu = 0.f;
    #pragma unroll
    for (int w = 0; w < 8; w++) mu += red1[w];
    mu *= (1.f / DMODEL);

    float d0 = x0 - mu, d1 = x1 - mu, d2 = x2 - mu, d3 = x3 - mu;
    float ss = d0 * d0 + d1 * d1 + d2 * d2 + d3 * d3;
    #pragma unroll
    for (int oo = 16; oo; oo >>= 1) ss += __shfl_xor_sync(0xffffffffu, ss, oo);
    if ((t & 31) == 0) red2[t >> 5] = ss;
    __syncthreads();

    float var = 0.f;
    #pragma unroll
    for (int w = 0; w < 8; w++) var += red2[w];
    var *= (1.f / DMODEL);

    const float rstd = rsqrtf(var + LN_EPS);

    float4 g = *(const float4*)(gamma + t * 4);
    float4 bb = *(const float4*)(beta + t * 4);
    float4 y;
    y.x = d0 * rstd * g.x + bb.x;
    y.y = d1 * rstd * g.y + bb.y;
    y.z = d2 * rstd * g.z + bb.z;
    y.w = d3 * rstd * g.w + bb.w;
    *(float4*)(out + off + t * 4) = y;
}

// ---------------------------------------------------------------------------
// Launcher: QKV GEMMs -> banded attention -> O-proj -> LN1 -> FFN1(GELU)
//           -> FFN2 -> LN2.  All plain kernel launches (graph-capturable).
// ---------------------------------------------------------------------------
extern "C" void kernel_launch(void* const* d_in, const int* in_sizes, int n_in,
                              void* d_out, int out_size)
{
    const float* x    = (const float*)d_in[0];
    const float* Wq   = (const float*)d_in[1];
    const float* bq   = (const float*)d_in[2];
    const float* Wk   = (const float*)d_in[3];
    const float* bk   = (const float*)d_in[4];
    const float* Wv   = (const float*)d_in[5];
    const float* bv   = (const float*)d_in[6];
    const float* Wo   = (const float*)d_in[7];
    const float* bo   = (const float*)d_in[8];
    const float* W1   = (const float*)d_in[9];
    const float* b1   = (const float*)d_in[10];
    const float* W2   = (const float*)d_in[11];
    const float* b2   = (const float*)d_in[12];
    const float* ln1g = (const float*)d_in[13];
    const float* ln1b = (const float*)d_in[14];
    const float* ln2g = (const float*)d_in[15];
    const float* ln2b = (const float*)d_in[16];
    float* out = (float*)d_out;

    float *Qp, *Kp, *Vp, *CTXp, *SAp, *X1p, *FF1p;
    cudaGetSymbolAddress((void**)&Qp,   g_Q);
    cudaGetSymbolAddress((void**)&Kp,   g_K);
    cudaGetSymbolAddress((void**)&Vp,   g_V);
    cudaGetSymbolAddress((void**)&CTXp, g_CTX);
    cudaGetSymbolAddress((void**)&SAp,  g_SA);
    cudaGetSymbolAddress((void**)&X1p,  g_X1);
    cudaGetSymbolAddress((void**)&FF1p, g_FF1);

    dim3 gD(DMODEL / 128, ROWS / 128);   // (8, 32) for N=1024 GEMMs
    dim3 gF(DFFN / 128,   ROWS / 128);   // (32, 32) for N=4096 GEMM

    // QKV projections
    sgemm_kernel<0><<<gD, 256>>>(x, Wq, bq, Qp, ROWS, DMODEL, DMODEL);
    sgemm_kernel<0><<<gD, 256>>>(x, Wk, bk, Kp, ROWS, DMODEL, DMODEL);
    sgemm_kernel<0><<<gD, 256>>>(x, Wv, bv, Vp, ROWS, DMODEL, DMODEL);

    // banded softmax attention
    dim3 ag(SEQ / 64, NH, BATCH);
    attn_kernel<<<ag, 64>>>(Qp, Kp, Vp, CTXp);

    // output projection + residual + LN1
    sgemm_kernel<0><<<gD, 256>>>(CTXp, Wo, bo, SAp, ROWS, DMODEL, DMODEL);
    add_ln_kernel<<<ROWS, 256>>>(SAp, x, ln1g, ln1b, X1p);

    // FFN
    sgemm_kernel<1><<<gF, 256>>>(X1p, W1, b1, FF1p, ROWS, DFFN, DMODEL);
    sgemm_kernel<0><<<gD, 256>>>(FF1p, W2, b2, SAp, ROWS, DMODEL, DFFN);
    add_ln_kernel<<<ROWS, 256>>>(SAp, X1p, ln2g, ln2b, out);
}

// round 4
// speedup vs baseline: 1.5227x; 1.5227x over previous
#include <cuda_runtime.h>
#include <math.h>
#include <stdint.h>

// ---------------------------------------------------------------------------
// Problem constants
// ---------------------------------------------------------------------------
#define BATCH   2
#define SEQ     2048
#define DMODEL  1024
#define NH      16
#define DH      64
#define DFFN    4096
#define ATT     256
#define ROWS    (BATCH * SEQ)   // 4096
#define LN_EPS  1e-5f
#define ATT_SCALE 0.022097086912079608f   // 1/sqrt(2048)

// ---------------------------------------------------------------------------
// Scratch
// ---------------------------------------------------------------------------
__device__ float g_Q  [ROWS * DMODEL];
__device__ float g_K  [ROWS * DMODEL];
__device__ float g_V  [ROWS * DMODEL];
__device__ float g_CTX[ROWS * DMODEL];
__device__ float g_SA [ROWS * DMODEL];
__device__ float g_X1 [ROWS * DMODEL];
__device__ float g_FF1[ROWS * DFFN];

// ---------------------------------------------------------------------------
// TF32 tensor-core GEMM: C = A[M,K] @ W[K,N] + bias (+ optional exact GELU)
// 128x128x16 block tile, 256 threads (8 warps 2x4), warp tile 64x32,
// mma.sync.m16n8k8.tf32 with cvt.rna rounding, cp.async double-buffered
// STATIC smem (37888 B < 48KB, no attribute calls needed).
//
// Conflict-free fragment reads:
//   As[m][k] stride 20  -> bank = (20g + t) mod 32 : all 32 lanes distinct
//   Bs[k][n] stride 136 -> bank = (8t + g)  mod 32 : all 32 lanes distinct
// ---------------------------------------------------------------------------
#define BM 128
#define BN 128
#define BK 16
#define AS_STRIDE 20
#define BS_STRIDE 136
#define A_FLOATS (BM * AS_STRIDE)          // 2560
#define B_FLOATS (BK * BS_STRIDE)          // 2176
#define BUF_FLOATS (A_FLOATS + B_FLOATS)   // 4736

__device__ __forceinline__ void cp_async16(uint32_t smem_addr, const void* gptr) {
    asm volatile("cp.async.cg.shared.global [%0], [%1], 16;\n"
                 :: "r"(smem_addr), "l"(gptr));
}
__device__ __forceinline__ void cp_commit() {
    asm volatile("cp.async.commit_group;\n");
}
template <int N>
__device__ __forceinline__ void cp_wait() {
    asm volatile("cp.async.wait_group %0;\n" :: "n"(N));
}

__device__ __forceinline__ uint32_t to_tf32(uint32_t x) {
    uint32_t r;
    asm("cvt.rna.tf32.f32 %0, %1;\n" : "=r"(r) : "r"(x));
    return r;
}

__device__ __forceinline__ void mma_tf32(float* c,
    uint32_t a0, uint32_t a1, uint32_t a2, uint32_t a3,
    uint32_t b0, uint32_t b1)
{
    asm volatile(
        "mma.sync.aligned.m16n8k8.row.col.f32.tf32.tf32.f32 "
        "{%0,%1,%2,%3}, {%4,%5,%6,%7}, {%8,%9}, {%0,%1,%2,%3};\n"
        : "+f"(c[0]), "+f"(c[1]), "+f"(c[2]), "+f"(c[3])
        : "r"(a0), "r"(a1), "r"(a2), "r"(a3), "r"(b0), "r"(b1));
}

template <int GELU>
__global__ __launch_bounds__(256) void gemm_tf32_kernel(
    const float* __restrict__ A, const float* __restrict__ W,
    const float* __restrict__ bias, float* __restrict__ C,
    int M, int N, int K)
{
    __shared__ __align__(16) float smem[2 * BUF_FLOATS];   // 37888 bytes

    const int tid  = threadIdx.x;
    const int lane = tid & 31;
    const int wid  = tid >> 5;
    const int g    = lane >> 2;   // 0..7
    const int t    = lane & 3;    // 0..3

    const int m0 = blockIdx.y * BM;
    const int n0 = blockIdx.x * BN;

    const int warpM = (wid & 1) * 64;
    const int warpN = (wid >> 1) * 32;

    const float* Ab = A + (size_t)m0 * K;
    const float* Wb = W + n0;

    // loaders: A tile 128x16 (2 float4/thread), B tile 16x128 (2 float4/thread)
    const int am = tid >> 2;            // 0..63
    const int ak = (tid & 3) * 4;       // 0,4,8,12
    const int bk = tid >> 5;            // 0..7
    const int bn = (tid & 31) * 4;      // 0..124

    uint32_t smem_base;
    asm("{ .reg .u64 x; cvta.to.shared.u64 x, %1; cvt.u32.u64 %0, x; }"
        : "=r"(smem_base) : "l"(smem));

    auto prefetch = [&](int k0, int buf) {
        uint32_t asm_base = smem_base + buf * (BUF_FLOATS * 4);
        uint32_t bsm_base = asm_base + A_FLOATS * 4;
        #pragma unroll
        for (int r = 0; r < 2; r++) {
            int m = am + r * 64;
            cp_async16(asm_base + (m * AS_STRIDE + ak) * 4,
                       Ab + (size_t)m * K + k0 + ak);
        }
        #pragma unroll
        for (int r = 0; r < 2; r++) {
            int kr = bk + r * 8;
            cp_async16(bsm_base + (kr * BS_STRIDE + bn) * 4,
                       Wb + (size_t)(k0 + kr) * N + bn);
        }
        cp_commit();
    };

    float acc[4][4][4];
    #pragma unroll
    for (int i = 0; i < 4; i++)
        #pragma unroll
        for (int j = 0; j < 4; j++)
            #pragma unroll
            for (int q = 0; q < 4; q++) acc[i][j][q] = 0.f;

    const int nIter = K / BK;
    prefetch(0, 0);

    for (int it = 0; it < nIter; it++) {
        if (it + 1 < nIter) {
            prefetch((it + 1) * BK, (it + 1) & 1);
            cp_wait<1>();
        } else {
            cp_wait<0>();
        }
        __syncthreads();

        const uint32_t* As_u = (const uint32_t*)(smem + (it & 1) * BUF_FLOATS);
        const uint32_t* Bs_u = As_u + A_FLOATS;

        #pragma unroll
        for (int ks = 0; ks < 2; ks++) {
            const int k8 = ks * 8;
            uint32_t af[4][4];
            #pragma unroll
            for (int mt = 0; mt < 4; mt++) {
                const int mr = warpM + mt * 16 + g;
                af[mt][0] = to_tf32(As_u[(mr    ) * AS_STRIDE + k8 + t]);
                af[mt][1] = to_tf32(As_u[(mr + 8) * AS_STRIDE + k8 + t]);
                af[mt][2] = to_tf32(As_u[(mr    ) * AS_STRIDE + k8 + t + 4]);
                af[mt][3] = to_tf32(As_u[(mr + 8) * AS_STRIDE + k8 + t + 4]);
            }
            uint32_t bf[4][2];
            #pragma unroll
            for (int nt = 0; nt < 4; nt++) {
                const int nc = warpN + nt * 8 + g;
                bf[nt][0] = to_tf32(Bs_u[(k8 + t    ) * BS_STRIDE + nc]);
                bf[nt][1] = to_tf32(Bs_u[(k8 + t + 4) * BS_STRIDE + nc]);
            }
            #pragma unroll
            for (int mt = 0; mt < 4; mt++)
                #pragma unroll
                for (int nt = 0; nt < 4; nt++)
                    mma_tf32(acc[mt][nt],
                             af[mt][0], af[mt][1], af[mt][2], af[mt][3],
                             bf[nt][0], bf[nt][1]);
        }
        __syncthreads();
    }

    // epilogue
    #pragma unroll
    for (int nt = 0; nt < 4; nt++) {
        const int col = n0 + warpN + nt * 8 + 2 * t;
        const float bi0 = bias[col];
        const float bi1 = bias[col + 1];
        #pragma unroll
        for (int mt = 0; mt < 4; mt++) {
            const int row = m0 + warpM + mt * 16 + g;
            float v0 = acc[mt][nt][0] + bi0;
            float v1 = acc[mt][nt][1] + bi1;
            float v2 = acc[mt][nt][2] + bi0;
            float v3 = acc[mt][nt][3] + bi1;
            if (GELU) {
                v0 = 0.5f * v0 * (1.0f + erff(v0 * 0.7071067811865475f));
                v1 = 0.5f * v1 * (1.0f + erff(v1 * 0.7071067811865475f));
                v2 = 0.5f * v2 * (1.0f + erff(v2 * 0.7071067811865475f));
                v3 = 0.5f * v3 * (1.0f + erff(v3 * 0.7071067811865475f));
            }
            *(float2*)(C + (size_t)row * N + col)       = make_float2(v0, v1);
            *(float2*)(C + (size_t)(row + 8) * N + col) = make_float2(v2, v3);
        }
    }
}

// ---------------------------------------------------------------------------
// Banded attention, 4 threads per query (16 channels each), 256-thread blocks.
// NOTE: shfl is executed UNCONDITIONALLY (warp-converged); the band mask only
// gates p. This fixes the R2 divergent-shfl deadlock.
// ---------------------------------------------------------------------------
__global__ __launch_bounds__(256) void attn_kernel(
    const float* __restrict__ Q, const float* __restrict__ Km,
    const float* __restrict__ Vm, float* __restrict__ CTX)
{
    __shared__ float4 Ks[64][16];
    __shared__ float4 Vs[64][16];

    const int tid = threadIdx.x;
    const int qi  = tid >> 2;       // 0..63 query in block
    const int c   = tid & 3;        // channel quarter
    const int i0  = blockIdx.x * 64;
    const int h   = blockIdx.y;
    const int b   = blockIdx.z;
    const int i   = i0 + qi;

    const size_t qoff = ((size_t)(b * SEQ + i) * DMODEL) + h * DH + c * 16;

    float4 q[4], o[4];
    #pragma unroll
    for (int cc = 0; cc < 4; cc++) {
        q[cc] = *(const float4*)(Q + qoff + cc * 4);
        o[cc] = make_float4(0.f, 0.f, 0.f, 0.f);
    }
    float l = 0.f;

    const int jlo = max(0, i0 - ATT);
    const int jhi = min(SEQ, i0 + 64 + ATT);

    for (int jt = jlo; jt < jhi; jt += 64) {
        for (int idx = tid; idx < 64 * 16; idx += 256) {
            const int row = idx >> 4;
            const int c4  = idx & 15;
            const size_t off =
                ((size_t)(b * SEQ + jt + row) * DMODEL) + h * DH + c4 * 4;
            Ks[row][c4] = *(const float4*)(Km + off);
            Vs[row][c4] = *(const float4*)(Vm + off);
        }
        __syncthreads();

        #pragma unroll 4
        for (int jj = 0; jj < 64; jj++) {
            const int j = jt + jj;
            float s = 0.f;
            #pragma unroll
            for (int cc = 0; cc < 4; cc++) {
                float4 kv = Ks[jj][c * 4 + cc];
                s += q[cc].x * kv.x + q[cc].y * kv.y
                   + q[cc].z * kv.z + q[cc].w * kv.w;
            }
            s += __shfl_xor_sync(0xffffffffu, s, 1);
            s += __shfl_xor_sync(0xffffffffu, s, 2);
            const bool inband = ((i - j) <= ATT) && ((j - i) <= ATT);
            const float p = inband ? __expf(s * ATT_SCALE) : 0.f;
            l += p;
            #pragma unroll
            for (int cc = 0; cc < 4; cc++) {
                float4 vv = Vs[jj][c * 4 + cc];
                o[cc].x += p * vv.x; o[cc].y += p * vv.y;
                o[cc].z += p * vv.z; o[cc].w += p * vv.w;
            }
        }
        __syncthreads();
    }

    const float inv = 1.f / l;
    #pragma unroll
    for (int cc = 0; cc < 4; cc++) {
        *(float4*)(CTX + qoff + cc * 4) =
            make_float4(o[cc].x * inv, o[cc].y * inv,
                        o[cc].z * inv, o[cc].w * inv);
    }
}

// ---------------------------------------------------------------------------
// Residual add + LayerNorm (D=1024), one block per row.
// ---------------------------------------------------------------------------
__global__ __launch_bounds__(256) void add_ln_kernel(
    const float* __restrict__ A, const float* __restrict__ R,
    const float* __restrict__ gamma, const float* __restrict__ beta,
    float* __restrict__ out)
{
    __shared__ float red1[8];
    __shared__ float red2[8];

    const int row = blockIdx.x;
    const int t   = threadIdx.x;
    const size_t off = (size_t)row * DMODEL;

    float4 a = *(const float4*)(A + off + t * 4);
    float4 r = *(const float4*)(R + off + t * 4);
    float x0 = a.x + r.x, x1 = a.y + r.y, x2 = a.z + r.z, x3 = a.w + r.w;

    float s = x0 + x1 + x2 + x3;
    #pragma unroll
    for (int oo = 16; oo; oo >>= 1) s += __shfl_xor_sync(0xffffffffu, s, oo);
    if ((t & 31) == 0) red1[t >> 5] = s;
    __syncthreads();

    float mu = 0.f;
    #pragma unroll
    for (int w = 0; w < 8; w++) mu += red1[w];
    mu *= (1.f / DMODEL);

    float d0 = x0 - mu, d1 = x1 - mu, d2 = x2 - mu, d3 = x3 - mu;
    float ss = d0 * d0 + d1 * d1 + d2 * d2 + d3 * d3;
    #pragma unroll
    for (int oo = 16; oo; oo >>= 1) ss += __shfl_xor_sync(0xffffffffu, ss, oo);
    if ((t & 31) == 0) red2[t >> 5] = ss;
    __syncthreads();

    float var = 0.f;
    #pragma unroll
    for (int w = 0; w < 8; w++) var += red2[w];
    var *= (1.f / DMODEL);

    const float rstd = rsqrtf(var + LN_EPS);

    float4 gm = *(const float4*)(gamma + t * 4);
    float4 bb = *(const float4*)(beta + t * 4);
    float4 y;
    y.x = d0 * rstd * gm.x + bb.x;
    y.y = d1 * rstd * gm.y + bb.y;
    y.z = d2 * rstd * gm.z + bb.z;
    y.w = d3 * rstd * gm.w + bb.w;
    *(float4*)(out + off + t * 4) = y;
}

// ---------------------------------------------------------------------------
// Launcher
// ---------------------------------------------------------------------------
extern "C" void kernel_launch(void* const* d_in, const int* in_sizes, int n_in,
                              void* d_out, int out_size)
{
    const float* x    = (const float*)d_in[0];
    const float* Wq   = (const float*)d_in[1];
    const float* bq   = (const float*)d_in[2];
    const float* Wk   = (const float*)d_in[3];
    const float* bk   = (const float*)d_in[4];
    const float* Wv   = (const float*)d_in[5];
    const float* bv   = (const float*)d_in[6];
    const float* Wo   = (const float*)d_in[7];
    const float* bo   = (const float*)d_in[8];
    const float* W1   = (const float*)d_in[9];
    const float* b1   = (const float*)d_in[10];
    const float* W2   = (const float*)d_in[11];
    const float* b2   = (const float*)d_in[12];
    const float* ln1g = (const float*)d_in[13];
    const float* ln1b = (const float*)d_in[14];
    const float* ln2g = (const float*)d_in[15];
    const float* ln2b = (const float*)d_in[16];
    float* out = (float*)d_out;

    float *Qp, *Kp, *Vp, *CTXp, *SAp, *X1p, *FF1p;
    cudaGetSymbolAddress((void**)&Qp,   g_Q);
    cudaGetSymbolAddress((void**)&Kp,   g_K);
    cudaGetSymbolAddress((void**)&Vp,   g_V);
    cudaGetSymbolAddress((void**)&CTXp, g_CTX);
    cudaGetSymbolAddress((void**)&SAp,  g_SA);
    cudaGetSymbolAddress((void**)&X1p,  g_X1);
    cudaGetSymbolAddress((void**)&FF1p, g_FF1);

    dim3 gD(DMODEL / BN, ROWS / BM);   // (8, 32)
    dim3 gF(DFFN / BN,   ROWS / BM);   // (32, 32)

    gemm_tf32_kernel<0><<<gD, 256>>>(x, Wq, bq, Qp, ROWS, DMODEL, DMODEL);
    gemm_tf32_kernel<0><<<gD, 256>>>(x, Wk, bk, Kp, ROWS, DMODEL, DMODEL);
    gemm_tf32_kernel<0><<<gD, 256>>>(x, Wv, bv, Vp, ROWS, DMODEL, DMODEL);

    dim3 ag(SEQ / 64, NH, BATCH);
    attn_kernel<<<ag, 256>>>(Qp, Kp, Vp, CTXp);

    gemm_tf32_kernel<0><<<gD, 256>>>(CTXp, Wo, bo, SAp, ROWS, DMODEL, DMODEL);
    add_ln_kernel<<<ROWS, 256>>>(SAp, x, ln1g, ln1b, X1p);

    gemm_tf32_kernel<1><<<gF, 256>>>(X1p, W1, b1, FF1p, ROWS, DFFN, DMODEL);
    gemm_tf32_kernel<0><<<gD, 256>>>(FF1p, W2, b2, SAp, ROWS, DMODEL, DFFN);
    add_ln_kernel<<<ROWS, 256>>>(SAp, X1p, ln2g, ln2b, out);
}

// round 7
// speedup vs baseline: 1.9321x; 1.2688x over previous
#include <cuda_runtime.h>
#include <math.h>
#include <stdint.h>

// ---------------------------------------------------------------------------
// Problem constants
// ---------------------------------------------------------------------------
#define BATCH   2
#define SEQ     2048
#define DMODEL  1024
#define NH      16
#define DH      64
#define DFFN    4096
#define ATT     256
#define ROWS    (BATCH * SEQ)   // 4096
#define LN_EPS  1e-5f
#define ATT_SCALE 0.022097086912079608f   // 1/sqrt(2048)

// tcgen05 only exists on the arch-accelerated ('a') targets.
#if defined(__CUDA_ARCH_FEAT_SM103_ALL) || defined(__CUDA_ARCH_FEAT_SM100_ALL) || defined(__CUDA_ARCH_FEAT_SM101_ALL)
#define HAS_TCGEN5 1
#else
#define HAS_TCGEN5 0
#endif

// ---------------------------------------------------------------------------
// Scratch (static device globals)
// ---------------------------------------------------------------------------
__device__ float g_Q  [ROWS * DMODEL];
__device__ float g_K  [ROWS * DMODEL];
__device__ float g_V  [ROWS * DMODEL];
__device__ float g_CTX[ROWS * DMODEL];
__device__ float g_SA [ROWS * DMODEL];
__device__ float g_X1 [ROWS * DMODEL];   // exact (residual path)
__device__ float g_X1r[ROWS * DMODEL];   // tf32-rounded (GEMM A operand)
__device__ float g_FF1[ROWS * DFFN];
__device__ float g_Xr [ROWS * DMODEL];   // tf32-rounded copy of x
__device__ float g_WTq[DMODEL * DMODEL]; // [N,K] transposed weights
__device__ float g_WTk[DMODEL * DMODEL];
__device__ float g_WTv[DMODEL * DMODEL];
__device__ float g_WTo[DMODEL * DMODEL];
__device__ float g_WT1[DFFN * DMODEL];
__device__ float g_WT2[DMODEL * DFFN];

// ---------------------------------------------------------------------------
// Helpers
// ---------------------------------------------------------------------------
__device__ __forceinline__ float tf32r(float x) {
    uint32_t u = __float_as_uint(x), r;
    asm("cvt.rna.tf32.f32 %0, %1;\n" : "=r"(r) : "r"(u));
    return __uint_as_float(r);
}

__device__ __forceinline__ uint32_t smem_u32(const void* p) {
    uint32_t a;
    asm("{ .reg .u64 x; cvta.to.shared.u64 x, %1; cvt.u32.u64 %0, x; }"
        : "=r"(a) : "l"(p));
    return a;
}

__device__ __forceinline__ void cp_async16(uint32_t dst, const void* src) {
    asm volatile("cp.async.cg.shared.global [%0], [%1], 16;\n"
                 :: "r"(dst), "l"(src));
}
__device__ __forceinline__ void cp_commit() {
    asm volatile("cp.async.commit_group;\n");
}
template <int N>
__device__ __forceinline__ void cp_wait() {
    asm volatile("cp.async.wait_group %0;\n" :: "n"(N));
}

#if HAS_TCGEN5
__device__ __forceinline__ uint32_t elect_one() {
    uint32_t pred;
    asm volatile("{\n\t.reg .pred p;\n\telect.sync _|p, 0xFFFFFFFF;\n\t"
                 "selp.b32 %0, 1, 0, p;\n\t}" : "=r"(pred));
    return pred;
}

// SW128 K-major smem descriptor
__device__ __forceinline__ uint64_t make_desc_sw128(uint32_t addr) {
    const uint64_t base =
        (uint64_t(2)  << 61) | (uint64_t(1) << 46) |
        (uint64_t(64) << 32) | (uint64_t(1) << 16);
    return base | ((uint64_t)(addr >> 4) & 0x3FFF);
}

// idesc: dtype=F32(1<<4), a=TF32(2<<7), b=TF32(2<<10), N=128(16<<17), M=128(8<<24)
#define IDESC_TF32 0x8200910u

__device__ __forceinline__ void mma_ss_tf32(
    uint32_t d_tmem, uint64_t a_desc, uint64_t b_desc, uint32_t en)
{
    uint32_t z = 0;
    asm volatile(
        "{\n\t.reg .pred p;\n\tsetp.ne.u32 p, %5, 0;\n\t"
        "tcgen05.mma.cta_group::1.kind::tf32 [%0], %1, %2, %3, {%4,%4,%4,%4}, p;\n\t}"
        :: "r"(d_tmem), "l"(a_desc), "l"(b_desc), "r"(IDESC_TF32),
           "r"(z), "r"(en)
        : "memory");
}

__device__ __forceinline__ void mbar_wait(uint32_t mb, uint32_t parity) {
    uint32_t done;
    asm volatile(
        "{\n\t.reg .pred p;\n\t"
        "mbarrier.try_wait.parity.acquire.cta.shared::cta.b64 p, [%1], %2;\n\t"
        "selp.b32 %0, 1, 0, p;\n\t}"
        : "=r"(done) : "r"(mb), "r"(parity) : "memory");
    if (!done) {
        asm volatile(
            "{\n\t.reg .pred P1;\n\t"
            "WAIT_LOOP_%=:\n\t"
            "mbarrier.try_wait.parity.acquire.cta.shared::cta.b64 P1, [%0], %1, 0x989680;\n\t"
            "@P1 bra.uni WAIT_DONE_%=;\n\t"
            "bra.uni WAIT_LOOP_%=;\n\t"
            "WAIT_DONE_%=:\n\t}"
            :: "r"(mb), "r"(parity) : "memory");
    }
}

__device__ __forceinline__ void ldtm_x32(uint32_t* r, uint32_t tmem_addr) {
    asm volatile(
        "tcgen05.ld.sync.aligned.32x32b.x32.b32 "
        "{%0, %1, %2, %3, %4, %5, %6, %7, "
        " %8, %9, %10, %11, %12, %13, %14, %15, "
        " %16, %17, %18, %19, %20, %21, %22, %23, "
        " %24, %25, %26, %27, %28, %29, %30, %31}, [%32];"
        : "=r"(r[0]),  "=r"(r[1]),  "=r"(r[2]),  "=r"(r[3]),
          "=r"(r[4]),  "=r"(r[5]),  "=r"(r[6]),  "=r"(r[7]),
          "=r"(r[8]),  "=r"(r[9]),  "=r"(r[10]), "=r"(r[11]),
          "=r"(r[12]), "=r"(r[13]), "=r"(r[14]), "=r"(r[15]),
          "=r"(r[16]), "=r"(r[17]), "=r"(r[18]), "=r"(r[19]),
          "=r"(r[20]), "=r"(r[21]), "=r"(r[22]), "=r"(r[23]),
          "=r"(r[24]), "=r"(r[25]), "=r"(r[26]), "=r"(r[27]),
          "=r"(r[28]), "=r"(r[29]), "=r"(r[30]), "=r"(r[31])
        : "r"(tmem_addr));
}
#endif  // HAS_TCGEN5

// ---------------------------------------------------------------------------
// GEMM: C[M,N] = A[M,K] @ BT[N,K]^T + bias (+GELU) (+tf32 round of output)
// CTA tile 128x128, BK=32 (128-byte K-major rows = SW128 atom), 128 threads,
// cp.async double-buffered. tcgen05 on 'a' targets, FFMA fallback otherwise.
// ---------------------------------------------------------------------------
#define TILE_B  16384
#define SM_A0   1024
#define SM_A1   (1024 + TILE_B)
#define SM_B0   (1024 + 2 * TILE_B)
#define SM_B1   (1024 + 3 * TILE_B)
#define GEMM_SMEM (1024 + 4 * TILE_B)   // 66560 bytes

template <int GELU, int ROUND>
__global__ __launch_bounds__(128) void gemm_tc(
    const float* __restrict__ A, const float* __restrict__ BT,
    const float* __restrict__ bias, float* __restrict__ C,
    int M, int N, int K)
{
    extern __shared__ __align__(1024) char smem[];
    const uint32_t sb = smem_u32(smem);
    const int tid = threadIdx.x;
    const int wid = tid >> 5;
    const int lid = tid & 31;
    const int m0 = blockIdx.y * 128;
    const int n0 = blockIdx.x * 128;

    const float* Ag = A + (size_t)m0 * K;
    const float* Bg = BT + (size_t)n0 * K;

    auto prefetch = [&](int it, int buf) {
        const int k0 = it * 32;
        const uint32_t abase = sb + (buf ? SM_A1 : SM_A0);
        const uint32_t bbase = sb + (buf ? SM_B1 : SM_B0);
        #pragma unroll
        for (int j = 0; j < 8; j++) {
            const int ch = j * 128 + tid;      // 1024 16B chunks per tile
            const int r  = ch >> 3;
            const int c  = ch & 7;
            const uint32_t off = r * 128 + c * 16;
            const uint32_t sw  = off ^ ((off >> 3) & 0x70);
            cp_async16(abase + sw, Ag + (size_t)r * K + k0 + c * 4);
            cp_async16(bbase + sw, Bg + (size_t)r * K + k0 + c * 4);
        }
        cp_commit();
    };

    const int nIter = K / 32;

#if HAS_TCGEN5
    // ---------------- tcgen05 path ----------------
    if (wid == 0) {
        asm volatile(
            "tcgen05.alloc.cta_group::1.sync.aligned.shared::cta.b32 [%0], %1;"
            :: "r"(sb + 0), "r"(128u) : "memory");
        asm volatile("tcgen05.relinquish_alloc_permit.cta_group::1.sync.aligned;");
    }
    if (tid == 0) {
        asm volatile("mbarrier.init.shared.b64 [%0], %1;" :: "r"(sb + 8),  "r"(1u) : "memory");
        asm volatile("mbarrier.init.shared.b64 [%0], %1;" :: "r"(sb + 16), "r"(1u) : "memory");
    }
    __syncthreads();

    uint32_t tmem;
    asm volatile("ld.shared.b32 %0, [%1];" : "=r"(tmem) : "r"(sb + 0));

    prefetch(0, 0);
    if (nIter > 1) prefetch(1, 1);

    int cnt0 = 0, cnt1 = 0;

    for (int it = 0; it < nIter; it++) {
        const int buf = it & 1;
        if (it + 1 < nIter) cp_wait<1>(); else cp_wait<0>();
        __syncthreads();

        if (wid == 0 && elect_one()) {
            asm volatile("fence.proxy.async.shared::cta;" ::: "memory");
            const uint64_t ad = make_desc_sw128(sb + (buf ? SM_A1 : SM_A0));
            const uint64_t bd = make_desc_sw128(sb + (buf ? SM_B1 : SM_B0));
            #pragma unroll
            for (int c = 0; c < 4; c++)
                mma_ss_tf32(tmem, ad + c * 2, bd + c * 2,
                            (it > 0 || c > 0) ? 1u : 0u);
            asm volatile(
                "tcgen05.commit.cta_group::1.mbarrier::arrive::one.shared::cluster.b64 [%0];"
                :: "r"(sb + 8 + buf * 8) : "memory");
        }

        if (it + 2 < nIter) {
            if (buf == 0) { mbar_wait(sb + 8,  cnt0 & 1); cnt0++; }
            else          { mbar_wait(sb + 16, cnt1 & 1); cnt1++; }
            prefetch(it + 2, buf);
        }
    }
    {
        const int b = (nIter - 1) & 1;
        if (b == 0) { mbar_wait(sb + 8,  cnt0 & 1); cnt0++; }
        else        { mbar_wait(sb + 16, cnt1 & 1); cnt1++; }
    }
    asm volatile("tcgen05.fence::after_thread_sync;" ::: "memory");

    // epilogue: each warp reads its 32-row subpartition
    const int row = m0 + wid * 32 + lid;
    float* Crow = C + (size_t)row * N + n0;
    #pragma unroll
    for (int base = 0; base < 128; base += 32) {
        uint32_t dr[32];
        ldtm_x32(dr, tmem + base);
        asm volatile("tcgen05.wait::ld.sync.aligned;" ::: "memory");
        float v[32];
        #pragma unroll
        for (int c = 0; c < 32; c++) {
            float t = __uint_as_float(dr[c]) + bias[n0 + base + c];
            if (GELU)
                t = 0.5f * t * (1.0f + erff(t * 0.7071067811865475f));
            if (ROUND) t = tf32r(t);
            v[c] = t;
        }
        #pragma unroll
        for (int c = 0; c < 32; c += 4)
            *(float4*)(Crow + base + c) =
                make_float4(v[c], v[c+1], v[c+2], v[c+3]);
    }
    asm volatile("tcgen05.fence::before_thread_sync;" ::: "memory");

    __syncthreads();
    if (tid == 0) {
        asm volatile("mbarrier.inval.shared.b64 [%0];" :: "r"(sb + 8)  : "memory");
        asm volatile("mbarrier.inval.shared.b64 [%0];" :: "r"(sb + 16) : "memory");
    }
    __syncthreads();
    if (wid == 0)
        asm volatile("tcgen05.dealloc.cta_group::1.sync.aligned.b32 %0, %1;"
                     :: "r"(tmem), "r"(128u));

#else
    // ---------------- FFMA fallback (non-'a' targets) ----------------
    const int ty = tid >> 4;   // 0..7  -> rows ty*16 .. +15
    const int tx = tid & 15;   // 0..15 -> cols tx*8 .. +7

    float acc[16][8];
    #pragma unroll
    for (int i = 0; i < 16; i++)
        #pragma unroll
        for (int j = 0; j < 8; j++) acc[i][j] = 0.f;

    prefetch(0, 0);
    if (nIter > 1) prefetch(1, 1);

    for (int it = 0; it < nIter; it++) {
        const int buf = it & 1;
        if (it + 1 < nIter) cp_wait<1>(); else cp_wait<0>();
        __syncthreads();

        const char* ab = smem + (buf ? SM_A1 : SM_A0);
        const char* bb = smem + (buf ? SM_B1 : SM_B0);

        #pragma unroll 4
        for (int kk = 0; kk < 32; kk++) {
            float a[16], b[8];
            #pragma unroll
            for (int i = 0; i < 16; i++) {
                const uint32_t off = (ty * 16 + i) * 128 + kk * 4;
                a[i] = *(const float*)(ab + (off ^ ((off >> 3) & 0x70)));
            }
            #pragma unroll
            for (int j = 0; j < 8; j++) {
                const uint32_t off = (tx * 8 + j) * 128 + kk * 4;
                b[j] = *(const float*)(bb + (off ^ ((off >> 3) & 0x70)));
            }
            #pragma unroll
            for (int i = 0; i < 16; i++)
                #pragma unroll
                for (int j = 0; j < 8; j++)
                    acc[i][j] += a[i] * b[j];
        }
        __syncthreads();
        if (it + 2 < nIter) prefetch(it + 2, buf);
    }

    #pragma unroll
    for (int i = 0; i < 16; i++) {
        const int row = m0 + ty * 16 + i;
        float* Crow = C + (size_t)row * N + n0 + tx * 8;
        float v[8];
        #pragma unroll
        for (int j = 0; j < 8; j++) {
            float t = acc[i][j] + bias[n0 + tx * 8 + j];
            if (GELU)
                t = 0.5f * t * (1.0f + erff(t * 0.7071067811865475f));
            if (ROUND) t = tf32r(t);
            v[j] = t;
        }
        *(float4*)(Crow)     = make_float4(v[0], v[1], v[2], v[3]);
        *(float4*)(Crow + 4) = make_float4(v[4], v[5], v[6], v[7]);
    }
#endif
}

// ---------------------------------------------------------------------------
// Weight transpose + tf32 round: out[n][k] = rna_tf32(in[k][n]); in [K,N]
// ---------------------------------------------------------------------------
__global__ __launch_bounds__(256) void transpose_round(
    const float* __restrict__ in, float* __restrict__ out, int K, int N)
{
    __shared__ float t[32][33];
    const int x0 = blockIdx.x * 32;
    const int y0 = blockIdx.y * 32;
    const int tx = threadIdx.x;
    const int ty = threadIdx.y;
    #pragma unroll
    for (int j = 0; j < 32; j += 8)
        t[ty + j][tx] = in[(size_t)(y0 + ty + j) * N + x0 + tx];
    __syncthreads();
    #pragma unroll
    for (int j = 0; j < 32; j += 8)
        out[(size_t)(x0 + ty + j) * K + y0 + tx] = tf32r(t[tx][ty + j]);
}

__global__ __launch_bounds__(256) void round_copy(
    const float* __restrict__ in, float* __restrict__ out, int n4)
{
    int i = blockIdx.x * blockDim.x + threadIdx.x;
    if (i < n4) {
        float4 v = ((const float4*)in)[i];
        v.x = tf32r(v.x); v.y = tf32r(v.y);
        v.z = tf32r(v.z); v.w = tf32r(v.w);
        ((float4*)out)[i] = v;
    }
}

// ---------------------------------------------------------------------------
// Banded attention, 4 threads per query (16 channels each), 256-thread blocks.
// ---------------------------------------------------------------------------
__global__ __launch_bounds__(256) void attn_kernel(
    const float* __restrict__ Q, const float* __restrict__ Km,
    const float* __restrict__ Vm, float* __restrict__ CTX)
{
    __shared__ float4 Ks[64][16];
    __shared__ float4 Vs[64][16];

    const int tid = threadIdx.x;
    const int qi  = tid >> 2;
    const int c   = tid & 3;
    const int i0  = blockIdx.x * 64;
    const int h   = blockIdx.y;
    const int b   = blockIdx.z;
    const int i   = i0 + qi;

    const size_t qoff = ((size_t)(b * SEQ + i) * DMODEL) + h * DH + c * 16;

    float4 q[4], o[4];
    #pragma unroll
    for (int cc = 0; cc < 4; cc++) {
        q[cc] = *(const float4*)(Q + qoff + cc * 4);
        o[cc] = make_float4(0.f, 0.f, 0.f, 0.f);
    }
    float l = 0.f;

    const int jlo = max(0, i0 - ATT);
    const int jhi = min(SEQ, i0 + 64 + ATT);

    for (int jt = jlo; jt < jhi; jt += 64) {
        for (int idx = tid; idx < 64 * 16; idx += 256) {
            const int row = idx >> 4;
            const int c4  = idx & 15;
            const size_t off =
                ((size_t)(b * SEQ + jt + row) * DMODEL) + h * DH + c4 * 4;
            Ks[row][c4] = *(const float4*)(Km + off);
            Vs[row][c4] = *(const float4*)(Vm + off);
        }
        __syncthreads();

        #pragma unroll 4
        for (int jj = 0; jj < 64; jj++) {
            const int j = jt + jj;
            float s = 0.f;
            #pragma unroll
            for (int cc = 0; cc < 4; cc++) {
                float4 kv = Ks[jj][c * 4 + cc];
                s += q[cc].x * kv.x + q[cc].y * kv.y
                   + q[cc].z * kv.z + q[cc].w * kv.w;
            }
            s += __shfl_xor_sync(0xffffffffu, s, 1);
            s += __shfl_xor_sync(0xffffffffu, s, 2);
            const bool inband = ((i - j) <= ATT) && ((j - i) <= ATT);
            const float p = inband ? __expf(s * ATT_SCALE) : 0.f;
            l += p;
            #pragma unroll
            for (int cc = 0; cc < 4; cc++) {
                float4 vv = Vs[jj][c * 4 + cc];
                o[cc].x += p * vv.x; o[cc].y += p * vv.y;
                o[cc].z += p * vv.z; o[cc].w += p * vv.w;
            }
        }
        __syncthreads();
    }

    const float inv = 1.f / l;
    #pragma unroll
    for (int cc = 0; cc < 4; cc++) {
        *(float4*)(CTX + qoff + cc * 4) =
            make_float4(tf32r(o[cc].x * inv), tf32r(o[cc].y * inv),
                        tf32r(o[cc].z * inv), tf32r(o[cc].w * inv));
    }
}

// ---------------------------------------------------------------------------
// Residual add + LayerNorm; optionally writes a second tf32-rounded copy
// (exact output feeds residual; rounded copy feeds the next GEMM).
// ---------------------------------------------------------------------------
template <int DUAL>
__global__ __launch_bounds__(256) void add_ln_kernel(
    const float* __restrict__ A, const float* __restrict__ R,
    const float* __restrict__ gamma, const float* __restrict__ beta,
    float* __restrict__ out, float* __restrict__ out_r)
{
    __shared__ float red1[8];
    __shared__ float red2[8];

    const int row = blockIdx.x;
    const int t   = threadIdx.x;
    const size_t off = (size_t)row * DMODEL;

    float4 a = *(const float4*)(A + off + t * 4);
    float4 r = *(const float4*)(R + off + t * 4);
    float x0 = a.x + r.x, x1 = a.y + r.y, x2 = a.z + r.z, x3 = a.w + r.w;

    float s = x0 + x1 + x2 + x3;
    #pragma unroll
    for (int oo = 16; oo; oo >>= 1) s += __shfl_xor_sync(0xffffffffu, s, oo);
    if ((t & 31) == 0) red1[t >> 5] = s;
    __syncthreads();

    float mu = 0.f;
    #pragma unroll
    for (int w = 0; w < 8; w++) mu += red1[w];
    mu *= (1.f / DMODEL);

    float d0 = x0 - mu, d1 = x1 - mu, d2 = x2 - mu, d3 = x3 - mu;
    float ss = d0 * d0 + d1 * d1 + d2 * d2 + d3 * d3;
    #pragma unroll
    for (int oo = 16; oo; oo >>= 1) ss += __shfl_xor_sync(0xffffffffu, ss, oo);
    if ((t & 31) == 0) red2[t >> 5] = ss;
    __syncthreads();

    float var = 0.f;
    #pragma unroll
    for (int w = 0; w < 8; w++) var += red2[w];
    var *= (1.f / DMODEL);

    const float rstd = rsqrtf(var + LN_EPS);

    float4 gm = *(const float4*)(gamma + t * 4);
    float4 bb = *(const float4*)(beta + t * 4);
    float y0 = d0 * rstd * gm.x + bb.x;
    float y1 = d1 * rstd * gm.y + bb.y;
    float y2 = d2 * rstd * gm.z + bb.z;
    float y3 = d3 * rstd * gm.w + bb.w;
    *(float4*)(out + off + t * 4) = make_float4(y0, y1, y2, y3);
    if (DUAL) {
        *(float4*)(out_r + off + t * 4) =
            make_float4(tf32r(y0), tf32r(y1), tf32r(y2), tf32r(y3));
    }
}

// ---------------------------------------------------------------------------
// Launcher
// ---------------------------------------------------------------------------
extern "C" void kernel_launch(void* const* d_in, const int* in_sizes, int n_in,
                              void* d_out, int out_size)
{
    const float* x    = (const float*)d_in[0];
    const float* Wq   = (const float*)d_in[1];
    const float* bq   = (const float*)d_in[2];
    const float* Wk   = (const float*)d_in[3];
    const float* bk   = (const float*)d_in[4];
    const float* Wv   = (const float*)d_in[5];
    const float* bv   = (const float*)d_in[6];
    const float* Wo   = (const float*)d_in[7];
    const float* bo   = (const float*)d_in[8];
    const float* W1   = (const float*)d_in[9];
    const float* b1   = (const float*)d_in[10];
    const float* W2   = (const float*)d_in[11];
    const float* b2   = (const float*)d_in[12];
    const float* ln1g = (const float*)d_in[13];
    const float* ln1b = (const float*)d_in[14];
    const float* ln2g = (const float*)d_in[15];
    const float* ln2b = (const float*)d_in[16];
    float* out = (float*)d_out;

    float *Qp, *Kp, *Vp, *CTXp, *SAp, *X1p, *X1rp, *FF1p, *Xrp;
    float *WTq, *WTk, *WTv, *WTo, *WT1, *WT2;
    cudaGetSymbolAddress((void**)&Qp,   g_Q);
    cudaGetSymbolAddress((void**)&Kp,   g_K);
    cudaGetSymbolAddress((void**)&Vp,   g_V);
    cudaGetSymbolAddress((void**)&CTXp, g_CTX);
    cudaGetSymbolAddress((void**)&SAp,  g_SA);
    cudaGetSymbolAddress((void**)&X1p,  g_X1);
    cudaGetSymbolAddress((void**)&X1rp, g_X1r);
    cudaGetSymbolAddress((void**)&FF1p, g_FF1);
    cudaGetSymbolAddress((void**)&Xrp,  g_Xr);
    cudaGetSymbolAddress((void**)&WTq,  g_WTq);
    cudaGetSymbolAddress((void**)&WTk,  g_WTk);
    cudaGetSymbolAddress((void**)&WTv,  g_WTv);
    cudaGetSymbolAddress((void**)&WTo,  g_WTo);
    cudaGetSymbolAddress((void**)&WT1,  g_WT1);
    cudaGetSymbolAddress((void**)&WT2,  g_WT2);

    cudaFuncSetAttribute(gemm_tc<0,0>,
        cudaFuncAttributeMaxDynamicSharedMemorySize, GEMM_SMEM);
    cudaFuncSetAttribute(gemm_tc<0,1>,
        cudaFuncAttributeMaxDynamicSharedMemorySize, GEMM_SMEM);
    cudaFuncSetAttribute(gemm_tc<1,1>,
        cudaFuncAttributeMaxDynamicSharedMemorySize, GEMM_SMEM);

    // weight transposes (+tf32 rounding) and rounded x
    dim3 tb(32, 8);
    transpose_round<<<dim3(DMODEL/32, DMODEL/32), tb>>>(Wq, WTq, DMODEL, DMODEL);
    transpose_round<<<dim3(DMODEL/32, DMODEL/32), tb>>>(Wk, WTk, DMODEL, DMODEL);
    transpose_round<<<dim3(DMODEL/32, DMODEL/32), tb>>>(Wv, WTv, DMODEL, DMODEL);
    transpose_round<<<dim3(DMODEL/32, DMODEL/32), tb>>>(Wo, WTo, DMODEL, DMODEL);
    transpose_round<<<dim3(DFFN/32,   DMODEL/32), tb>>>(W1, WT1, DMODEL, DFFN);
    transpose_round<<<dim3(DMODEL/32, DFFN/32),   tb>>>(W2, WT2, DFFN, DMODEL);
    round_copy<<<(ROWS * DMODEL / 4 + 255) / 256, 256>>>(x, Xrp, ROWS * DMODEL / 4);

    dim3 gD(DMODEL / 128, ROWS / 128);   // (8, 32)
    dim3 gF(DFFN / 128,   ROWS / 128);   // (32, 32)

    gemm_tc<0,0><<<gD, 128, GEMM_SMEM>>>(Xrp, WTq, bq, Qp, ROWS, DMODEL, DMODEL);
    gemm_tc<0,0><<<gD, 128, GEMM_SMEM>>>(Xrp, WTk, bk, Kp, ROWS, DMODEL, DMODEL);
    gemm_tc<0,0><<<gD, 128, GEMM_SMEM>>>(Xrp, WTv, bv, Vp, ROWS, DMODEL, DMODEL);

    dim3 ag(SEQ / 64, NH, BATCH);
    attn_kernel<<<ag, 256>>>(Qp, Kp, Vp, CTXp);

    gemm_tc<0,0><<<gD, 128, GEMM_SMEM>>>(CTXp, WTo, bo, SAp, ROWS, DMODEL, DMODEL);
    add_ln_kernel<1><<<ROWS, 256>>>(SAp, x, ln1g, ln1b, X1p, X1rp);

    gemm_tc<1,1><<<gF, 128, GEMM_SMEM>>>(X1rp, WT1, b1, FF1p, ROWS, DFFN, DMODEL);
    gemm_tc<0,0><<<gD, 128, GEMM_SMEM>>>(FF1p, WT2, b2, SAp, ROWS, DMODEL, DFFN);
    add_ln_kernel<0><<<ROWS, 256>>>(SAp, X1p, ln2g, ln2b, out, nullptr);
}

// round 8
// speedup vs baseline: 1.9925x; 1.0313x over previous
#include <cuda_runtime.h>
#include <math.h>
#include <stdint.h>

// ---------------------------------------------------------------------------
// Problem constants
// ---------------------------------------------------------------------------
#define BATCH   2
#define SEQ     2048
#define DMODEL  1024
#define NH      16
#define DH      64
#define DFFN    4096
#define ATT     256
#define ROWS    (BATCH * SEQ)   // 4096
#define LN_EPS  1e-5f
#define ATT_SCALE 0.022097086912079608f   // 1/sqrt(2048)

// tcgen05 only exists on the arch-accelerated ('a') targets.
#if defined(__CUDA_ARCH_FEAT_SM103_ALL) || defined(__CUDA_ARCH_FEAT_SM100_ALL) || defined(__CUDA_ARCH_FEAT_SM101_ALL)
#define HAS_TCGEN5 1
#else
#define HAS_TCGEN5 0
#endif

// ---------------------------------------------------------------------------
// Scratch (static device globals)
// ---------------------------------------------------------------------------
__device__ float g_Q  [ROWS * DMODEL];
__device__ float g_K  [ROWS * DMODEL];
__device__ float g_V  [ROWS * DMODEL];
__device__ float g_CTX[ROWS * DMODEL];
__device__ float g_SA [ROWS * DMODEL];
__device__ float g_X1 [ROWS * DMODEL];   // exact (residual path)
__device__ float g_X1r[ROWS * DMODEL];   // tf32-rounded (GEMM A operand)
__device__ float g_FF1[ROWS * DFFN];
__device__ float g_Xr [ROWS * DMODEL];   // tf32-rounded copy of x
__device__ float g_WTq[DMODEL * DMODEL]; // [N,K] transposed weights
__device__ float g_WTk[DMODEL * DMODEL];
__device__ float g_WTv[DMODEL * DMODEL];
__device__ float g_WTo[DMODEL * DMODEL];
__device__ float g_WT1[DFFN * DMODEL];
__device__ float g_WT2[DMODEL * DFFN];

// ---------------------------------------------------------------------------
// Helpers
// ---------------------------------------------------------------------------
__device__ __forceinline__ float tf32r(float x) {
    uint32_t u = __float_as_uint(x), r;
    asm("cvt.rna.tf32.f32 %0, %1;\n" : "=r"(r) : "r"(u));
    return __uint_as_float(r);
}

__device__ __forceinline__ uint32_t smem_u32(const void* p) {
    uint32_t a;
    asm("{ .reg .u64 x; cvta.to.shared.u64 x, %1; cvt.u32.u64 %0, x; }"
        : "=r"(a) : "l"(p));
    return a;
}

__device__ __forceinline__ void cp_async16(uint32_t dst, const void* src) {
    asm volatile("cp.async.cg.shared.global [%0], [%1], 16;\n"
                 :: "r"(dst), "l"(src));
}
__device__ __forceinline__ void cp_commit() {
    asm volatile("cp.async.commit_group;\n");
}
template <int N>
__device__ __forceinline__ void cp_wait() {
    asm volatile("cp.async.wait_group %0;\n" :: "n"(N));
}

#if HAS_TCGEN5
__device__ __forceinline__ uint32_t elect_one() {
    uint32_t pred;
    asm volatile("{\n\t.reg .pred p;\n\telect.sync _|p, 0xFFFFFFFF;\n\t"
                 "selp.b32 %0, 1, 0, p;\n\t}" : "=r"(pred));
    return pred;
}

// SW128 K-major smem descriptor
__device__ __forceinline__ uint64_t make_desc_sw128(uint32_t addr) {
    const uint64_t base =
        (uint64_t(2)  << 61) | (uint64_t(1) << 46) |
        (uint64_t(64) << 32) | (uint64_t(1) << 16);
    return base | ((uint64_t)(addr >> 4) & 0x3FFF);
}

// idesc: dtype=F32(1<<4), a=TF32(2<<7), b=TF32(2<<10), N=128(16<<17), M=128(8<<24)
#define IDESC_TF32 0x8200910u

__device__ __forceinline__ void mma_ss_tf32(
    uint32_t d_tmem, uint64_t a_desc, uint64_t b_desc, uint32_t en)
{
    uint32_t z = 0;
    asm volatile(
        "{\n\t.reg .pred p;\n\tsetp.ne.u32 p, %5, 0;\n\t"
        "tcgen05.mma.cta_group::1.kind::tf32 [%0], %1, %2, %3, {%4,%4,%4,%4}, p;\n\t}"
        :: "r"(d_tmem), "l"(a_desc), "l"(b_desc), "r"(IDESC_TF32),
           "r"(z), "r"(en)
        : "memory");
}

__device__ __forceinline__ void mbar_wait(uint32_t mb, uint32_t parity) {
    uint32_t done;
    asm volatile(
        "{\n\t.reg .pred p;\n\t"
        "mbarrier.try_wait.parity.acquire.cta.shared::cta.b64 p, [%1], %2;\n\t"
        "selp.b32 %0, 1, 0, p;\n\t}"
        : "=r"(done) : "r"(mb), "r"(parity) : "memory");
    if (!done) {
        asm volatile(
            "{\n\t.reg .pred P1;\n\t"
            "WAIT_LOOP_%=:\n\t"
            "mbarrier.try_wait.parity.acquire.cta.shared::cta.b64 P1, [%0], %1, 0x989680;\n\t"
            "@P1 bra.uni WAIT_DONE_%=;\n\t"
            "bra.uni WAIT_LOOP_%=;\n\t"
            "WAIT_DONE_%=:\n\t}"
            :: "r"(mb), "r"(parity) : "memory");
    }
}

__device__ __forceinline__ void ldtm_x32(uint32_t* r, uint32_t tmem_addr) {
    asm volatile(
        "tcgen05.ld.sync.aligned.32x32b.x32.b32 "
        "{%0, %1, %2, %3, %4, %5, %6, %7, "
        " %8, %9, %10, %11, %12, %13, %14, %15, "
        " %16, %17, %18, %19, %20, %21, %22, %23, "
        " %24, %25, %26, %27, %28, %29, %30, %31}, [%32];"
        : "=r"(r[0]),  "=r"(r[1]),  "=r"(r[2]),  "=r"(r[3]),
          "=r"(r[4]),  "=r"(r[5]),  "=r"(r[6]),  "=r"(r[7]),
          "=r"(r[8]),  "=r"(r[9]),  "=r"(r[10]), "=r"(r[11]),
          "=r"(r[12]), "=r"(r[13]), "=r"(r[14]), "=r"(r[15]),
          "=r"(r[16]), "=r"(r[17]), "=r"(r[18]), "=r"(r[19]),
          "=r"(r[20]), "=r"(r[21]), "=r"(r[22]), "=r"(r[23]),
          "=r"(r[24]), "=r"(r[25]), "=r"(r[26]), "=r"(r[27]),
          "=r"(r[28]), "=r"(r[29]), "=r"(r[30]), "=r"(r[31])
        : "r"(tmem_addr));
}
#endif  // HAS_TCGEN5

// ---------------------------------------------------------------------------
// GEMM: C[M,N] = A[M,K] @ BT[N,K]^T + bias (+GELU) (+tf32 round of output)
// CTA tile 128x128, BK=32 (128-byte K-major rows = SW128 atom), 128 threads.
// THREE-stage cp.async pipeline: prefetch(it+2) reuses the stage of it-1, so
// the mbarrier wait covers the MMA of the PREVIOUS iteration -> the current
// MMA overlaps with the next loads (fixes R7's per-iter tensor-pipe drain).
// ---------------------------------------------------------------------------
#define TILE_B  16384
#define STAGE_B (2 * TILE_B)                 // A + B per stage
#define GEMM_SMEM (1024 + 3 * STAGE_B)       // 99328 bytes

template <int GELU, int ROUND>
__global__ __launch_bounds__(128) void gemm_tc(
    const float* __restrict__ A, const float* __restrict__ BT,
    const float* __restrict__ bias, float* __restrict__ C,
    int M, int N, int K)
{
    extern __shared__ __align__(1024) char smem[];
    const uint32_t sb = smem_u32(smem);
    const int tid = threadIdx.x;
    const int wid = tid >> 5;
    const int lid = tid & 31;
    const int m0 = blockIdx.y * 128;
    const int n0 = blockIdx.x * 128;

    const float* Ag = A + (size_t)m0 * K;
    const float* Bg = BT + (size_t)n0 * K;

    auto prefetch = [&](int it, int stage) {
        const int k0 = it * 32;
        const uint32_t abase = sb + 1024 + stage * STAGE_B;
        const uint32_t bbase = abase + TILE_B;
        #pragma unroll
        for (int j = 0; j < 8; j++) {
            const int ch = j * 128 + tid;      // 1024 16B chunks per tile
            const int r  = ch >> 3;
            const int c  = ch & 7;
            const uint32_t off = r * 128 + c * 16;
            const uint32_t sw  = off ^ ((off >> 3) & 0x70);
            cp_async16(abase + sw, Ag + (size_t)r * K + k0 + c * 4);
            cp_async16(bbase + sw, Bg + (size_t)r * K + k0 + c * 4);
        }
        cp_commit();
    };

    const int nIter = K / 32;

#if HAS_TCGEN5
    // ---------------- tcgen05 path ----------------
    if (wid == 0) {
        asm volatile(
            "tcgen05.alloc.cta_group::1.sync.aligned.shared::cta.b32 [%0], %1;"
            :: "r"(sb + 0), "r"(128u) : "memory");
        asm volatile("tcgen05.relinquish_alloc_permit.cta_group::1.sync.aligned;");
    }
    if (tid == 0) {
        asm volatile("mbarrier.init.shared.b64 [%0], %1;" :: "r"(sb + 8),  "r"(1u) : "memory");
        asm volatile("mbarrier.init.shared.b64 [%0], %1;" :: "r"(sb + 16), "r"(1u) : "memory");
        asm volatile("mbarrier.init.shared.b64 [%0], %1;" :: "r"(sb + 24), "r"(1u) : "memory");
    }
    __syncthreads();

    uint32_t tmem;
    asm volatile("ld.shared.b32 %0, [%1];" : "=r"(tmem) : "r"(sb + 0));

    prefetch(0, 0);
    if (nIter > 1) prefetch(1, 1);

    int cnt0 = 0, cnt1 = 0, cnt2 = 0;

    for (int it = 0; it < nIter; it++) {
        const int s = it % 3;
        if (it + 1 < nIter) cp_wait<1>(); else cp_wait<0>();
        __syncthreads();

        if (wid == 0 && elect_one()) {
            asm volatile("fence.proxy.async.shared::cta;" ::: "memory");
            const uint64_t ad = make_desc_sw128(sb + 1024 + s * STAGE_B);
            const uint64_t bd = make_desc_sw128(sb + 1024 + s * STAGE_B + TILE_B);
            #pragma unroll
            for (int c = 0; c < 4; c++)
                mma_ss_tf32(tmem, ad + c * 2, bd + c * 2,
                            (it > 0 || c > 0) ? 1u : 0u);
            asm volatile(
                "tcgen05.commit.cta_group::1.mbarrier::arrive::one.shared::cluster.b64 [%0];"
                :: "r"(sb + 8 + s * 8) : "memory");
        }

        if (it + 2 < nIter) {
            const int ws = (it + 2) % 3;     // == (it-1)%3 : previous iter's MMA
            if (it >= 1) {
                if (ws == 0)      { mbar_wait(sb + 8,  cnt0 & 1); cnt0++; }
                else if (ws == 1) { mbar_wait(sb + 16, cnt1 & 1); cnt1++; }
                else              { mbar_wait(sb + 24, cnt2 & 1); cnt2++; }
            }
            prefetch(it + 2, ws);
        }
    }
    {   // wait for the last commit: covers all prior MMAs
        const int ls = (nIter - 1) % 3;
        if (ls == 0)      { mbar_wait(sb + 8,  cnt0 & 1); cnt0++; }
        else if (ls == 1) { mbar_wait(sb + 16, cnt1 & 1); cnt1++; }
        else              { mbar_wait(sb + 24, cnt2 & 1); cnt2++; }
    }
    asm volatile("tcgen05.fence::after_thread_sync;" ::: "memory");

    // epilogue: each warp reads its 32-row subpartition
    const int row = m0 + wid * 32 + lid;
    float* Crow = C + (size_t)row * N + n0;
    #pragma unroll
    for (int base = 0; base < 128; base += 32) {
        uint32_t dr[32];
        ldtm_x32(dr, tmem + base);
        asm volatile("tcgen05.wait::ld.sync.aligned;" ::: "memory");
        float v[32];
        #pragma unroll
        for (int c = 0; c < 32; c++) {
            float t = __uint_as_float(dr[c]) + bias[n0 + base + c];
            if (GELU)
                t = 0.5f * t * (1.0f + erff(t * 0.7071067811865475f));
            if (ROUND) t = tf32r(t);
            v[c] = t;
        }
        #pragma unroll
        for (int c = 0; c < 32; c += 4)
            *(float4*)(Crow + base + c) =
                make_float4(v[c], v[c+1], v[c+2], v[c+3]);
    }
    asm volatile("tcgen05.fence::before_thread_sync;" ::: "memory");

    __syncthreads();
    if (tid == 0) {
        asm volatile("mbarrier.inval.shared.b64 [%0];" :: "r"(sb + 8)  : "memory");
        asm volatile("mbarrier.inval.shared.b64 [%0];" :: "r"(sb + 16) : "memory");
        asm volatile("mbarrier.inval.shared.b64 [%0];" :: "r"(sb + 24) : "memory");
    }
    __syncthreads();
    if (wid == 0)
        asm volatile("tcgen05.dealloc.cta_group::1.sync.aligned.b32 %0, %1;"
                     :: "r"(tmem), "r"(128u));

#else
    // ---------------- FFMA fallback (non-'a' targets) ----------------
    const int ty = tid >> 4;   // 0..7  -> rows ty*16 .. +15
    const int tx = tid & 15;   // 0..15 -> cols tx*8 .. +7

    float acc[16][8];
    #pragma unroll
    for (int i = 0; i < 16; i++)
        #pragma unroll
        for (int j = 0; j < 8; j++) acc[i][j] = 0.f;

    prefetch(0, 0);
    if (nIter > 1) prefetch(1, 1);

    for (int it = 0; it < nIter; it++) {
        const int s = it % 3;
        if (it + 1 < nIter) cp_wait<1>(); else cp_wait<0>();
        __syncthreads();

        const char* ab = smem + 1024 + s * STAGE_B;
        const char* bb = ab + TILE_B;

        #pragma unroll 4
        for (int kk = 0; kk < 32; kk++) {
            float a[16], b[8];
            #pragma unroll
            for (int i = 0; i < 16; i++) {
                const uint32_t off = (ty * 16 + i) * 128 + kk * 4;
                a[i] = *(const float*)(ab + (off ^ ((off >> 3) & 0x70)));
            }
            #pragma unroll
            for (int j = 0; j < 8; j++) {
                const uint32_t off = (tx * 8 + j) * 128 + kk * 4;
                b[j] = *(const float*)(bb + (off ^ ((off >> 3) & 0x70)));
            }
            #pragma unroll
            for (int i = 0; i < 16; i++)
                #pragma unroll
                for (int j = 0; j < 8; j++)
                    acc[i][j] += a[i] * b[j];
        }
        __syncthreads();
        if (it + 2 < nIter) prefetch(it + 2, (it + 2) % 3);
    }

    #pragma unroll
    for (int i = 0; i < 16; i++) {
        const int row = m0 + ty * 16 + i;
        float* Crow = C + (size_t)row * N + n0 + tx * 8;
        float v[8];
        #pragma unroll
        for (int j = 0; j < 8; j++) {
            float t = acc[i][j] + bias[n0 + tx * 8 + j];
            if (GELU)
                t = 0.5f * t * (1.0f + erff(t * 0.7071067811865475f));
            if (ROUND) t = tf32r(t);
            v[j] = t;
        }
        *(float4*)(Crow)     = make_float4(v[0], v[1], v[2], v[3]);
        *(float4*)(Crow + 4) = make_float4(v[4], v[5], v[6], v[7]);
    }
#endif
}

// ---------------------------------------------------------------------------
// Weight transpose + tf32 round: out[n][k] = rna_tf32(in[k][n]); in [K,N]
// ---------------------------------------------------------------------------
__global__ __launch_bounds__(256) void transpose_round(
    const float* __restrict__ in, float* __restrict__ out, int K, int N)
{
    __shared__ float t[32][33];
    const int x0 = blockIdx.x * 32;
    const int y0 = blockIdx.y * 32;
    const int tx = threadIdx.x;
    const int ty = threadIdx.y;
    #pragma unroll
    for (int j = 0; j < 32; j += 8)
        t[ty + j][tx] = in[(size_t)(y0 + ty + j) * N + x0 + tx];
    __syncthreads();
    #pragma unroll
    for (int j = 0; j < 32; j += 8)
        out[(size_t)(x0 + ty + j) * K + y0 + tx] = tf32r(t[tx][ty + j]);
}

__global__ __launch_bounds__(256) void round_copy(
    const float* __restrict__ in, float* __restrict__ out, int n4)
{
    int i = blockIdx.x * blockDim.x + threadIdx.x;
    if (i < n4) {
        float4 v = ((const float4*)in)[i];
        v.x = tf32r(v.x); v.y = tf32r(v.y);
        v.z = tf32r(v.z); v.w = tf32r(v.w);
        ((float4*)out)[i] = v;
    }
}

// ---------------------------------------------------------------------------
// Banded attention, 4 threads per query (16 channels each), 256-thread blocks.
// ---------------------------------------------------------------------------
__global__ __launch_bounds__(256) void attn_kernel(
    const float* __restrict__ Q, const float* __restrict__ Km,
    const float* __restrict__ Vm, float* __restrict__ CTX)
{
    __shared__ float4 Ks[64][16];
    __shared__ float4 Vs[64][16];

    const int tid = threadIdx.x;
    const int qi  = tid >> 2;
    const int c   = tid & 3;
    const int i0  = blockIdx.x * 64;
    const int h   = blockIdx.y;
    const int b   = blockIdx.z;
    const int i   = i0 + qi;

    const size_t qoff = ((size_t)(b * SEQ + i) * DMODEL) + h * DH + c * 16;

    float4 q[4], o[4];
    #pragma unroll
    for (int cc = 0; cc < 4; cc++) {
        q[cc] = *(const float4*)(Q + qoff + cc * 4);
        o[cc] = make_float4(0.f, 0.f, 0.f, 0.f);
    }
    float l = 0.f;

    const int jlo = max(0, i0 - ATT);
    const int jhi = min(SEQ, i0 + 64 + ATT);

    for (int jt = jlo; jt < jhi; jt += 64) {
        for (int idx = tid; idx < 64 * 16; idx += 256) {
            const int row = idx >> 4;
            const int c4  = idx & 15;
            const size_t off =
                ((size_t)(b * SEQ + jt + row) * DMODEL) + h * DH + c4 * 4;
            Ks[row][c4] = *(const float4*)(Km + off);
            Vs[row][c4] = *(const float4*)(Vm + off);
        }
        __syncthreads();

        #pragma unroll 4
        for (int jj = 0; jj < 64; jj++) {
            const int j = jt + jj;
            float s = 0.f;
            #pragma unroll
            for (int cc = 0; cc < 4; cc++) {
                float4 kv = Ks[jj][c * 4 + cc];
                s += q[cc].x * kv.x + q[cc].y * kv.y
                   + q[cc].z * kv.z + q[cc].w * kv.w;
            }
            s += __shfl_xor_sync(0xffffffffu, s, 1);
            s += __shfl_xor_sync(0xffffffffu, s, 2);
            const bool inband = ((i - j) <= ATT) && ((j - i) <= ATT);
            const float p = inband ? __expf(s * ATT_SCALE) : 0.f;
            l += p;
            #pragma unroll
            for (int cc = 0; cc < 4; cc++) {
                float4 vv = Vs[jj][c * 4 + cc];
                o[cc].x += p * vv.x; o[cc].y += p * vv.y;
                o[cc].z += p * vv.z; o[cc].w += p * vv.w;
            }
        }
        __syncthreads();
    }

    const float inv = 1.f / l;
    #pragma unroll
    for (int cc = 0; cc < 4; cc++) {
        *(float4*)(CTX + qoff + cc * 4) =
            make_float4(tf32r(o[cc].x * inv), tf32r(o[cc].y * inv),
                        tf32r(o[cc].z * inv), tf32r(o[cc].w * inv));
    }
}

// ---------------------------------------------------------------------------
// Residual add + LayerNorm; optionally writes a second tf32-rounded copy
// (exact output feeds residual; rounded copy feeds the next GEMM).
// ---------------------------------------------------------------------------
template <int DUAL>
__global__ __launch_bounds__(256) void add_ln_kernel(
    const float* __restrict__ A, const float* __restrict__ R,
    const float* __restrict__ gamma, const float* __restrict__ beta,
    float* __restrict__ out, float* __restrict__ out_r)
{
    __shared__ float red1[8];
    __shared__ float red2[8];

    const int row = blockIdx.x;
    const int t   = threadIdx.x;
    const size_t off = (size_t)row * DMODEL;

    float4 a = *(const float4*)(A + off + t * 4);
    float4 r = *(const float4*)(R + off + t * 4);
    float x0 = a.x + r.x, x1 = a.y + r.y, x2 = a.z + r.z, x3 = a.w + r.w;

    float s = x0 + x1 + x2 + x3;
    #pragma unroll
    for (int oo = 16; oo; oo >>= 1) s += __shfl_xor_sync(0xffffffffu, s, oo);
    if ((t & 31) == 0) red1[t >> 5] = s;
    __syncthreads();

    float mu = 0.f;
    #pragma unroll
    for (int w = 0; w < 8; w++) mu += red1[w];
    mu *= (1.f / DMODEL);

    float d0 = x0 - mu, d1 = x1 - mu, d2 = x2 - mu, d3 = x3 - mu;
    float ss = d0 * d0 + d1 * d1 + d2 * d2 + d3 * d3;
    #pragma unroll
    for (int oo = 16; oo; oo >>= 1) ss += __shfl_xor_sync(0xffffffffu, ss, oo);
    if ((t & 31) == 0) red2[t >> 5] = ss;
    __syncthreads();

    float var = 0.f;
    #pragma unroll
    for (int w = 0; w < 8; w++) var += red2[w];
    var *= (1.f / DMODEL);

    const float rstd = rsqrtf(var + LN_EPS);

    float4 gm = *(const float4*)(gamma + t * 4);
    float4 bb = *(const float4*)(beta + t * 4);
    float y0 = d0 * rstd * gm.x + bb.x;
    float y1 = d1 * rstd * gm.y + bb.y;
    float y2 = d2 * rstd * gm.z + bb.z;
    float y3 = d3 * rstd * gm.w + bb.w;
    *(float4*)(out + off + t * 4) = make_float4(y0, y1, y2, y3);
    if (DUAL) {
        *(float4*)(out_r + off + t * 4) =
            make_float4(tf32r(y0), tf32r(y1), tf32r(y2), tf32r(y3));
    }
}

// ---------------------------------------------------------------------------
// Launcher
// ---------------------------------------------------------------------------
extern "C" void kernel_launch(void* const* d_in, const int* in_sizes, int n_in,
                              void* d_out, int out_size)
{
    const float* x    = (const float*)d_in[0];
    const float* Wq   = (const float*)d_in[1];
    const float* bq   = (const float*)d_in[2];
    const float* Wk   = (const float*)d_in[3];
    const float* bk   = (const float*)d_in[4];
    const float* Wv   = (const float*)d_in[5];
    const float* bv   = (const float*)d_in[6];
    const float* Wo   = (const float*)d_in[7];
    const float* bo   = (const float*)d_in[8];
    const float* W1   = (const float*)d_in[9];
    const float* b1   = (const float*)d_in[10];
    const float* W2   = (const float*)d_in[11];
    const float* b2   = (const float*)d_in[12];
    const float* ln1g = (const float*)d_in[13];
    const float* ln1b = (const float*)d_in[14];
    const float* ln2g = (const float*)d_in[15];
    const float* ln2b = (const float*)d_in[16];
    float* out = (float*)d_out;

    float *Qp, *Kp, *Vp, *CTXp, *SAp, *X1p, *X1rp, *FF1p, *Xrp;
    float *WTq, *WTk, *WTv, *WTo, *WT1, *WT2;
    cudaGetSymbolAddress((void**)&Qp,   g_Q);
    cudaGetSymbolAddress((void**)&Kp,   g_K);
    cudaGetSymbolAddress((void**)&Vp,   g_V);
    cudaGetSymbolAddress((void**)&CTXp, g_CTX);
    cudaGetSymbolAddress((void**)&SAp,  g_SA);
    cudaGetSymbolAddress((void**)&X1p,  g_X1);
    cudaGetSymbolAddress((void**)&X1rp, g_X1r);
    cudaGetSymbolAddress((void**)&FF1p, g_FF1);
    cudaGetSymbolAddress((void**)&Xrp,  g_Xr);
    cudaGetSymbolAddress((void**)&WTq,  g_WTq);
    cudaGetSymbolAddress((void**)&WTk,  g_WTk);
    cudaGetSymbolAddress((void**)&WTv,  g_WTv);
    cudaGetSymbolAddress((void**)&WTo,  g_WTo);
    cudaGetSymbolAddress((void**)&WT1,  g_WT1);
    cudaGetSymbolAddress((void**)&WT2,  g_WT2);

    cudaFuncSetAttribute(gemm_tc<0,0>,
        cudaFuncAttributeMaxDynamicSharedMemorySize, GEMM_SMEM);
    cudaFuncSetAttribute(gemm_tc<0,1>,
        cudaFuncAttributeMaxDynamicSharedMemorySize, GEMM_SMEM);
    cudaFuncSetAttribute(gemm_tc<1,1>,
        cudaFuncAttributeMaxDynamicSharedMemorySize, GEMM_SMEM);

    // weight transposes (+tf32 rounding) and rounded x
    dim3 tb(32, 8);
    transpose_round<<<dim3(DMODEL/32, DMODEL/32), tb>>>(Wq, WTq, DMODEL, DMODEL);
    transpose_round<<<dim3(DMODEL/32, DMODEL/32), tb>>>(Wk, WTk, DMODEL, DMODEL);
    transpose_round<<<dim3(DMODEL/32, DMODEL/32), tb>>>(Wv, WTv, DMODEL, DMODEL);
    transpose_round<<<dim3(DMODEL/32, DMODEL/32), tb>>>(Wo, WTo, DMODEL, DMODEL);
    transpose_round<<<dim3(DFFN/32,   DMODEL/32), tb>>>(W1, WT1, DMODEL, DFFN);
    transpose_round<<<dim3(DMODEL/32, DFFN/32),   tb>>>(W2, WT2, DFFN, DMODEL);
    round_copy<<<(ROWS * DMODEL / 4 + 255) / 256, 256>>>(x, Xrp, ROWS * DMODEL / 4);

    dim3 gD(DMODEL / 128, ROWS / 128);   // (8, 32)
    dim3 gF(DFFN / 128,   ROWS / 128);   // (32, 32)

    gemm_tc<0,0><<<gD, 128, GEMM_SMEM>>>(Xrp, WTq, bq, Qp, ROWS, DMODEL, DMODEL);
    gemm_tc<0,0><<<gD, 128, GEMM_SMEM>>>(Xrp, WTk, bk, Kp, ROWS, DMODEL, DMODEL);
    gemm_tc<0,0><<<gD, 128, GEMM_SMEM>>>(Xrp, WTv, bv, Vp, ROWS, DMODEL, DMODEL);

    dim3 ag(SEQ / 64, NH, BATCH);
    attn_kernel<<<ag, 256>>>(Qp, Kp, Vp, CTXp);

    gemm_tc<0,0><<<gD, 128, GEMM_SMEM>>>(CTXp, WTo, bo, SAp, ROWS, DMODEL, DMODEL);
    add_ln_kernel<1><<<ROWS, 256>>>(SAp, x, ln1g, ln1b, X1p, X1rp);

    gemm_tc<1,1><<<gF, 128, GEMM_SMEM>>>(X1rp, WT1, b1, FF1p, ROWS, DFFN, DMODEL);
    gemm_tc<0,0><<<gD, 128, GEMM_SMEM>>>(FF1p, WT2, b2, SAp, ROWS, DMODEL, DFFN);
    add_ln_kernel<0><<<ROWS, 256>>>(SAp, X1p, ln2g, ln2b, out, nullptr);
}